// round 14
// baseline (speedup 1.0000x reference)
#include <cuda_runtime.h>
#include <cuda_fp16.h>
#include <cstdint>

#define NROWS 65536
#define D 128
#define TMAX 2048

// smem: rp 4KB | 3 stages x (A 16KB + W 16KB)
#define A_OFF   4096
#define STAGE   32768
#define SMEM_SZ (4096 + 3 * 32768)

// ---------------- scratch ----------------
__device__ __half g_G16[(size_t)2 * NROWS * 512];   // per row: [r_sum | z_sum | inn | hn]
__device__ __half g_mem16[2][(size_t)NROWS * D];
__device__ __half g_feat16[2][(size_t)NROWS * D];
__device__ __half g_TEtab16[2 * TMAX * D];
__device__ __half g_Wih16[2][384 * 512];
__device__ __half g_Whh16[2][384 * 128];
__device__ int g_hidx[NROWS], g_gidx[NROWS], g_trel[NROWS];
__device__ int g_sync[2 * 512];

// ---------------- ptx helpers ----------------
__device__ __forceinline__ void mma_f16(float* c, const uint32_t* a, uint32_t b0, uint32_t b1) {
    asm volatile(
        "mma.sync.aligned.m16n8k16.row.col.f32.f16.f16.f32 "
        "{%0,%1,%2,%3}, {%4,%5,%6,%7}, {%8,%9}, {%0,%1,%2,%3};\n"
        : "+f"(c[0]), "+f"(c[1]), "+f"(c[2]), "+f"(c[3])
        : "r"(a[0]), "r"(a[1]), "r"(a[2]), "r"(a[3]), "r"(b0), "r"(b1));
}
__device__ __forceinline__ void cp16(uint32_t dst, const void* src) {
    asm volatile("cp.async.cg.shared.global [%0], [%1], 16;\n" :: "r"(dst), "l"(src));
}
__device__ __forceinline__ void ldsm4(uint32_t* r, uint32_t addr) {
    asm volatile("ldmatrix.sync.aligned.m8n8.x4.shared.b16 {%0,%1,%2,%3}, [%4];"
                 : "=r"(r[0]), "=r"(r[1]), "=r"(r[2]), "=r"(r[3]) : "r"(addr));
}

// ---------------- unified setup kernel ----------------
// grid segments (256 threads each):
//  [0,16384)      conv_mem
//  [16384,32768)  feat pick/gather (pick computed inline)
//  [32768,34688)  weight fp16 rounding
//  [34688,35712)  TE cos tables
//  [35712,35968)  prep descriptors + last_up + g_sync reset
__global__ void setup_kernel(const int* __restrict__ n_id,
                             const int* __restrict__ other_s, const int* __restrict__ other_d,
                             const int* __restrict__ t_s, const int* __restrict__ t_d,
                             const int* __restrict__ last_update,
                             const float* __restrict__ memory, const float* __restrict__ pos_mem,
                             const float* __restrict__ pos_emb,
                             const float* __restrict__ msg_s, const float* __restrict__ msg_d,
                             const float* __restrict__ wm, const float* __restrict__ bm,
                             const float* __restrict__ wp, const float* __restrict__ bp,
                             const float* __restrict__ Wih0, const float* __restrict__ Wih1,
                             const float* __restrict__ Whh0, const float* __restrict__ Whh1,
                             float* __restrict__ out)
{
    int b = blockIdx.x, tid = threadIdx.x;
    if (b < 16384) {
        // ---- convert memory/pos_mem to fp16 ----
        int arr = b >> 13;
        const float* s = arr ? pos_mem : memory;
        __half* d = g_mem16[arr];
        size_t i = ((size_t)(b & 8191) * 256 + tid) * 4;
        float4 v = *(const float4*)(s + i);
        *(__half2*)(d + i)     = __floats2half2_rn(v.x, v.y);
        *(__half2*)(d + i + 2) = __floats2half2_rn(v.z, v.w);
    } else if (b < 32768) {
        // ---- feature pick/gather + convert ----
        int warp = tid >> 5, lane = tid & 31;
        int row = (b - 16384) * 4 + (warp >> 1);
        int br  = warp & 1;
        bool pick = (t_s[row] >= t_d[row]);
        const float* src;
        if (br == 0) src = (pick ? msg_s : msg_d) + (size_t)row * D;
        else {
            int fidx = pick ? n_id[row] : other_d[row];
            src = pos_emb + (size_t)fidx * D;
        }
        float4 v = *(const float4*)(src + lane * 4);
        __half* d = g_feat16[br] + (size_t)row * D + lane * 4;
        *(__half2*)d       = __floats2half2_rn(v.x, v.y);
        *(__half2*)(d + 2) = __floats2half2_rn(v.z, v.w);
    } else if (b < 34688) {
        // ---- round weights to fp16 ----
        int wb = b - 32768;
        int which; int local;
        if (wb < 768)       { which = 0; local = wb; }
        else if (wb < 1536) { which = 1; local = wb - 768; }
        else if (wb < 1728) { which = 2; local = wb - 1536; }
        else                { which = 3; local = wb - 1728; }
        const float* s = (which == 0) ? Wih0 : (which == 1) ? Wih1 : (which == 2) ? Whh0 : Whh1;
        __half* d      = (which == 0) ? g_Wih16[0] : (which == 1) ? g_Wih16[1]
                       : (which == 2) ? g_Whh16[0] : g_Whh16[1];
        int i = local * 256 + tid;
        d[i] = __float2half_rn(s[i]);
    } else if (b < 35712) {
        // ---- TE cos tables ----
        int t = (b - 34688) * 2 + (tid >> 7);
        int k = tid & 127;
        float tf = (float)t;
        g_TEtab16[t * D + k]            = __float2half_rn(cosf(tf * wm[k] + bm[k]));
        g_TEtab16[TMAX * D + t * D + k] = __float2half_rn(cosf(tf * wp[k] + bp[k]));
    } else {
        // ---- prep descriptors + last_up + sync reset ----
        int idx = (b - 35712) * 256 + tid;
        if (idx < 1024) g_sync[idx] = 0;
        int row = idx;
        int ts = t_s[row], td = t_d[row];
        bool pick = (ts >= td);
        int nid = n_id[row];
        int tpick = pick ? ts : td;
        g_hidx[row] = nid;
        g_gidx[row] = pick ? other_s[row] : other_d[row];
        g_trel[row] = tpick - last_update[nid];
        out[(size_t)2 * NROWS * D + row] = (float)tpick;
    }
}

// ---------------- pipelined FP16 GEMM + fused last-CTA GRU ----------------
// grid (2048, 2): blockIdx.x = rb*4 + nb (gate CTAs of a rowblock are adjacent/co-scheduled)
// BM=128, BN=128, BK=64, 512 threads, 4x4 warp grid m32n32, 3-stage cp.async.
// gates: nb0=r_sum (10 slabs: 8 Wih + 2 Whh), nb1=z_sum (10), nb2=inn (8), nb3=hn (2)
__global__ void __launch_bounds__(512, 2)
gemm16_kernel(const float* __restrict__ memory, const float* __restrict__ pos_mem,
              const float* __restrict__ bih0, const float* __restrict__ bhh0,
              const float* __restrict__ bih1, const float* __restrict__ bhh1,
              float* __restrict__ out)
{
    extern __shared__ char sm[];
    const __half** rp = (const __half**)sm;
    uint32_t su = (uint32_t)__cvta_generic_to_shared(sm);

    int br = blockIdx.y;
    int nb = blockIdx.x & 3;
    int rb = blockIdx.x >> 2;
    int NSslab = (nb == 3) ? 2 : ((nb == 2) ? 8 : 10);
    int whh_base = (nb < 2) ? nb * 128 : 256;

    const __half* WihB = g_Wih16[br];
    const __half* WhhB = g_Whh16[br];

    int tid = threadIdx.x, lane = tid & 31, warp = tid >> 5;
    int wm = warp & 3, wn = warp >> 2;

    if (tid < 128) {
        int R = rb * 128 + tid;
        rp[tid]       = g_mem16[br] + (size_t)g_hidx[R] * D;
        rp[128 + tid] = g_mem16[br] + (size_t)g_gidx[R] * D;
        rp[256 + tid] = g_feat16[br] + (size_t)R * D;
        rp[384 + tid] = g_TEtab16 + (size_t)br * TMAX * D + (size_t)g_trel[R] * D;
    }
    __syncthreads();

    auto issue = [&](int s) {
        if (s < NSslab) {
            int st = s % 3;
            bool is_wih = (nb <= 2) && (s < 8);
            int c     = is_wih ? (s >> 1) : 0;
            int koffA = is_wih ? (s & 1) * 128 : ((nb < 2) ? (s - 8) : s) * 128;  // bytes
            uint32_t base = su + A_OFF + st * STAGE;
            #pragma unroll
            for (int p = 0; p < 2; ++p) {
                int g = tid + p * 512;
                int row = g >> 3, j = g & 7;
                int jp = ((j ^ (row & 7)) << 4);
                cp16(base + g * 16, (const char*)rp[c * 128 + row] + koffA + jp);
                const char* wsrc;
                if (is_wih) wsrc = (const char*)(WihB + (size_t)(nb * 128 + row) * 512) + s * 128 + jp;
                else        wsrc = (const char*)(WhhB + (size_t)(whh_base + row) * 128) + koffA + jp;
                cp16(base + 16384 + g * 16, wsrc);
            }
        }
        asm volatile("cp.async.commit_group;\n");
    };

    // fragment lane constants (row&7 == lane&7 for all tiles)
    int x7 = lane & 7;
    int a_kh = lane >> 4;
    int b_kh = (lane >> 3) & 1;
    uint32_t aRow = (uint32_t)((wm * 32 + ((lane >> 3) & 1) * 8 + (lane & 7)) * 128);
    uint32_t bRow = (uint32_t)((wn * 32 + (lane >> 4) * 8 + (lane & 7)) * 128);

    float acc[2][4][4];
    #pragma unroll
    for (int i = 0; i < 2; ++i)
        #pragma unroll
        for (int j = 0; j < 4; ++j)
            #pragma unroll
            for (int q = 0; q < 4; ++q) acc[i][j][q] = 0.f;

    issue(0);
    issue(1);

    for (int s = 0; s < NSslab; ++s) {
        asm volatile("cp.async.wait_group 1;\n");
        __syncthreads();
        issue(s + 2);

        uint32_t aSt = su + A_OFF + (s % 3) * STAGE;
        uint32_t wSt = aSt + 16384;
        #pragma unroll
        for (int s2 = 0; s2 < 4; ++s2) {
            uint32_t aj = (uint32_t)(((s2 * 2 + a_kh) ^ x7) << 4);
            uint32_t bj = (uint32_t)(((s2 * 2 + b_kh) ^ x7) << 4);
            uint32_t Af[2][4];
            #pragma unroll
            for (int mf = 0; mf < 2; ++mf)
                ldsm4(Af[mf], aSt + aRow + mf * 2048 + aj);
            uint32_t Bf[2][4];
            #pragma unroll
            for (int p = 0; p < 2; ++p)
                ldsm4(Bf[p], wSt + bRow + p * 2048 + bj);
            #pragma unroll
            for (int nf = 0; nf < 4; ++nf) {
                uint32_t b0 = Bf[nf >> 1][(nf & 1) * 2];
                uint32_t b1 = Bf[nf >> 1][(nf & 1) * 2 + 1];
                #pragma unroll
                for (int mf = 0; mf < 2; ++mf)
                    mma_f16(&acc[mf][nf][0], Af[mf], b0, b1);
            }
        }
    }

    // store gate slice to G16
    size_t gb = (size_t)br * NROWS * 512;
    #pragma unroll
    for (int mf = 0; mf < 2; ++mf) {
        int r = rb * 128 + wm * 32 + mf * 16 + (lane >> 2);
        #pragma unroll
        for (int nf = 0; nf < 4; ++nf) {
            int col = nb * 128 + wn * 32 + nf * 8 + (lane & 3) * 2;
            *(__half2*)&g_G16[gb + (size_t)r * 512 + col]       = __floats2half2_rn(acc[mf][nf][0], acc[mf][nf][1]);
            *(__half2*)&g_G16[gb + (size_t)(r + 8) * 512 + col] = __floats2half2_rn(acc[mf][nf][2], acc[mf][nf][3]);
        }
    }

    // ---------------- fused GRU: last of the 4 gate-CTAs does the epilogue ----------------
    __threadfence();
    __syncthreads();
    __shared__ int s_win;
    if (tid == 0)
        s_win = (atomicAdd(&g_sync[br * 512 + rb], 1) == 3);
    __syncthreads();
    if (s_win) {
        __threadfence();
        const float* mem = br ? pos_mem : memory;
        const float* bih = br ? bih1 : bih0;
        const float* bhh = br ? bhh1 : bhh0;
        int row = tid >> 2;
        int R   = rb * 128 + row;
        int c0  = (tid & 3) * 32;
        const __half* G   = g_G16 + gb + (size_t)R * 512;
        const float* hrow = mem + (size_t)g_hidx[R] * D;
        float* op = out + ((size_t)br * NROWS + R) * D;
        #pragma unroll
        for (int jc = 0; jc < 8; ++jc) {
            int j = c0 + jc * 4;
            uint2 grv = *(const uint2*)&G[j];
            uint2 gzv = *(const uint2*)&G[128 + j];
            uint2 giv = *(const uint2*)&G[256 + j];
            uint2 ghv = *(const uint2*)&G[384 + j];
            float gr[4], gz[4], gi[4], gh[4];
            {
                float2 a = __half22float2(*(__half2*)&grv.x), b = __half22float2(*(__half2*)&grv.y);
                gr[0] = a.x; gr[1] = a.y; gr[2] = b.x; gr[3] = b.y;
                a = __half22float2(*(__half2*)&gzv.x); b = __half22float2(*(__half2*)&gzv.y);
                gz[0] = a.x; gz[1] = a.y; gz[2] = b.x; gz[3] = b.y;
                a = __half22float2(*(__half2*)&giv.x); b = __half22float2(*(__half2*)&giv.y);
                gi[0] = a.x; gi[1] = a.y; gi[2] = b.x; gi[3] = b.y;
                a = __half22float2(*(__half2*)&ghv.x); b = __half22float2(*(__half2*)&ghv.y);
                gh[0] = a.x; gh[1] = a.y; gh[2] = b.x; gh[3] = b.y;
            }
            float4 b1r = *(const float4*)&bih[j],       b2r = *(const float4*)&bhh[j];
            float4 b1z = *(const float4*)&bih[128 + j], b2z = *(const float4*)&bhh[128 + j];
            float4 b1n = *(const float4*)&bih[256 + j], b2n = *(const float4*)&bhh[256 + j];
            float4 hv  = *(const float4*)&hrow[j];
            const float* b1rp = &b1r.x; const float* b2rp = &b2r.x;
            const float* b1zp = &b1z.x; const float* b2zp = &b2z.x;
            const float* b1np = &b1n.x; const float* b2np = &b2n.x;
            const float* hp = &hv.x;
            float o[4];
            #pragma unroll
            for (int q = 0; q < 4; ++q) {
                float r = 1.f / (1.f + expf(-(gr[q] + b1rp[q] + b2rp[q])));
                float z = 1.f / (1.f + expf(-(gz[q] + b1zp[q] + b2zp[q])));
                float n = tanhf(gi[q] + b1np[q] + r * (gh[q] + b2np[q]));
                o[q] = (1.f - z) * n + z * hp[q];
            }
            *(float4*)&op[j] = make_float4(o[0], o[1], o[2], o[3]);
        }
    }
}

// ---------------- launch ----------------
extern "C" void kernel_launch(void* const* d_in, const int* in_sizes, int n_in,
                              void* d_out, int out_size)
{
    const int*   n_id        = (const int*)  d_in[0];
    const float* memory      = (const float*)d_in[1];
    const float* pos_mem     = (const float*)d_in[2];
    const float* pos_emb     = (const float*)d_in[3];
    const float* raw_msg_s   = (const float*)d_in[4];
    const float* raw_msg_d   = (const float*)d_in[5];
    const int*   other_s     = (const int*)  d_in[6];
    const int*   other_d     = (const int*)  d_in[7];
    const int*   t_s         = (const int*)  d_in[8];
    const int*   t_d         = (const int*)  d_in[9];
    const int*   last_update = (const int*)  d_in[10];
    const float* w_time_mem  = (const float*)d_in[11];
    const float* b_time_mem  = (const float*)d_in[12];
    const float* w_time_pos  = (const float*)d_in[13];
    const float* b_time_pos  = (const float*)d_in[14];
    const float* Wih_mem     = (const float*)d_in[15];
    const float* Whh_mem     = (const float*)d_in[16];
    const float* bih_mem     = (const float*)d_in[17];
    const float* bhh_mem     = (const float*)d_in[18];
    const float* Wih_pos     = (const float*)d_in[19];
    const float* Whh_pos     = (const float*)d_in[20];
    const float* bih_pos     = (const float*)d_in[21];
    const float* bhh_pos     = (const float*)d_in[22];
    float* out = (float*)d_out;

    cudaFuncSetAttribute(gemm16_kernel, cudaFuncAttributeMaxDynamicSharedMemorySize, SMEM_SZ);

    setup_kernel<<<35968, 256>>>(n_id, other_s, other_d, t_s, t_d, last_update,
                                 memory, pos_mem, pos_emb, raw_msg_s, raw_msg_d,
                                 w_time_mem, b_time_mem, w_time_pos, b_time_pos,
                                 Wih_mem, Wih_pos, Whh_mem, Whh_pos, out);

    gemm16_kernel<<<dim3(2048, 2), 512, SMEM_SZ>>>(
        memory, pos_mem, bih_mem, bhh_mem, bih_pos, bhh_pos, out);
}